// round 12
// baseline (speedup 1.0000x reference)
#include <cuda_runtime.h>

// Problem constants
constexpr int NN = 20000;    // nodes
constexpr int NE = 640000;   // edges
constexpr int LAT = 64;
constexpr int HID = 128;
constexpr int NF  = 64;

// ---------------- scratch (device globals; no allocation allowed) -----------
__device__ int   g_is64;
__device__ int   g_src32[NE];
__device__ int   g_dst32[NE];
__device__ int   g_deg[NN];
__device__ int   g_rowptr[NN + 1];
__device__ int   g_cursor[NN];
__device__ int   g_bsum[32];
__device__ int   g_boff[32];
__device__ int   g_srcs[NE];        // src node per edge, sorted by dst (CSR)
__device__ float g_X[NN * HID];     // layer input features
__device__ float g_H[NN * HID];     // transformed features h = x @ W^T
__device__ float g_es[NN];          // h . a_s per node
__device__ float g_ed[NN];          // h . a_d per node

__device__ __forceinline__ int clampN(int v) {
    v = v < 0 ? 0 : v;
    return v >= NN ? NN - 1 : v;
}

// ---------------- CSR build ------------------------------------------------
__global__ __launch_bounds__(256) void k_zero_deg() {
    int i = blockIdx.x * blockDim.x + threadIdx.x;
    if (i < NN) g_deg[i] = 0;
    if (i == 0) g_is64 = 0;
}

// int64 node ids (< 2^31, >= 0) => every odd int32 word of first 2*NE words is 0.
__global__ __launch_bounds__(256) void k_detect(const int* __restrict__ e) {
    int i = blockIdx.x * blockDim.x + threadIdx.x;
    int v = (i < NE) ? e[2 * i + 1] : 0;
    #pragma unroll
    for (int o = 16; o; o >>= 1) v |= __shfl_xor_sync(0xffffffffu, v, o);
    if ((threadIdx.x & 31) == 0 && v != 0) atomicOr(&g_is64, 1);
}

// fused convert + degree histogram
__global__ __launch_bounds__(256) void k_convert_hist(const int* __restrict__ e) {
    int i = blockIdx.x * blockDim.x + threadIdx.x;
    if (i >= NE) return;
    int s, d;
    if (g_is64 == 0) {   // all high words zero -> int64 layout
        const long long* e64 = (const long long*)e;
        s = (int)e64[i];
        d = (int)e64[NE + i];
    } else {             // int32 layout
        s = e[i];
        d = e[NE + i];
    }
    s = clampN(s); d = clampN(d);
    g_src32[i] = s;
    g_dst32[i] = d;
    atomicAdd(&g_deg[d], 1);
}

// ---- multi-block exclusive scan: local scan -> block sums -> add offsets ---
__global__ __launch_bounds__(1024) void k_scan1() {
    __shared__ int wsum[32];
    __shared__ int woff[32];
    const int tid = threadIdx.x, lane = tid & 31, wid = tid >> 5;
    const int i = blockIdx.x * 1024 + tid;
    int v = (i < NN) ? g_deg[i] : 0;
    int x = v;
    #pragma unroll
    for (int o = 1; o < 32; o <<= 1) {
        int y = __shfl_up_sync(0xffffffffu, x, o);
        if (lane >= o) x += y;
    }
    if (lane == 31) wsum[wid] = x;
    __syncthreads();
    if (wid == 0) {
        int w = wsum[lane];
        int incl = w;
        #pragma unroll
        for (int o = 1; o < 32; o <<= 1) {
            int y = __shfl_up_sync(0xffffffffu, incl, o);
            if (lane >= o) incl += y;
        }
        woff[lane] = incl - w;
        if (lane == 31) g_bsum[blockIdx.x] = incl;
    }
    __syncthreads();
    int incl = x + woff[wid];
    if (i < NN) g_rowptr[i + 1] = incl;      // block-local inclusive
}

__global__ __launch_bounds__(32) void k_scan2(int nblk) {
    int lane = threadIdx.x;
    int v = (lane < nblk) ? g_bsum[lane] : 0;
    int incl = v;
    #pragma unroll
    for (int o = 1; o < 32; o <<= 1) {
        int y = __shfl_up_sync(0xffffffffu, incl, o);
        if (lane >= o) incl += y;
    }
    if (lane < nblk) g_boff[lane] = incl - v;   // exclusive
    if (lane == 0) g_rowptr[0] = 0;
}

__global__ __launch_bounds__(1024) void k_scan3() {
    const int i = blockIdx.x * 1024 + threadIdx.x;
    if (i < NN) {
        int rp = g_rowptr[i + 1] + g_boff[blockIdx.x];
        g_rowptr[i + 1] = rp;
        g_cursor[i] = rp - g_deg[i];
    }
}

__global__ __launch_bounds__(256) void k_scatter() {
    int i = blockIdx.x * blockDim.x + threadIdx.x;
    if (i < NE) {
        int d = g_dst32[i];
        int pos = atomicAdd(&g_cursor[d], 1);
        if (pos >= 0 && pos < NE) g_srcs[pos] = g_src32[i];
    }
}

// ---------------- fc: x = relu(z @ fc_w.T + fc_b) into g_X -----------------
__global__ __launch_bounds__(256) void k_fc(const float* __restrict__ w,
                                            const float* __restrict__ b,
                                            const float* __restrict__ z) {
    const int wid  = (blockIdx.x * blockDim.x + threadIdx.x) >> 5;
    const int lane = threadIdx.x & 31;
    const int half = lane >> 4;
    const int sub  = lane & 15;
    const int row  = wid * 2 + half;
    if (row >= NN * LAT) return;

    float4 wv = ((const float4*)(w + (size_t)row * LAT))[sub];
    float4 zv = ((const float4*)z)[sub];
    float acc = wv.x * zv.x + wv.y * zv.y + wv.z * zv.z + wv.w * zv.w;
    #pragma unroll
    for (int o = 8; o; o >>= 1) acc += __shfl_xor_sync(0xffffffffu, acc, o);
    if (sub == 0) {
        acc += b[row];
        g_X[row] = acc > 0.f ? acc : 0.f;
    }
}

// ---------------- GEMM + fused attention coefficients ----------------------
// H[n][f] = dot(X[n][:FIN], W[f][:FIN]); also es[n]=H[n]·a_s, ed[n]=H[n]·a_d
// computed in-register (half-warp shuffle reduction over the 16 c-threads).
template <int FIN, int FOUT>
__global__ __launch_bounds__(256) void k_gemm(const float* __restrict__ X,
                                              const float* __restrict__ W,
                                              const float* __restrict__ as_,
                                              const float* __restrict__ ad_,
                                              float* __restrict__ Hout) {
    constexpr int KT = 32;
    constexpr int XP = 64 + 4;
    constexpr int WP = FOUT + 4;
    constexpr int NJ = FOUT / 64;
    __shared__ float Xs[KT * XP];
    __shared__ float Ws[KT * WP];
    const int tid = threadIdx.x;
    const int r = tid >> 4;           // 0..15 -> nodes 4r..4r+3
    const int c = tid & 15;           // cols 4c..4c+3 (+64 if NJ==2)
    const int nodeBase = blockIdx.x * 64;

    float acc[4][NJ][4];
    #pragma unroll
    for (int i = 0; i < 4; i++)
        #pragma unroll
        for (int j = 0; j < NJ; j++)
            #pragma unroll
            for (int q = 0; q < 4; q++) acc[i][j][q] = 0.f;

    for (int kt = 0; kt < FIN; kt += KT) {
        #pragma unroll
        for (int l = tid; l < 64 * KT; l += 256) {
            int n = l >> 5, k = l & 31;
            int node = nodeBase + n;
            Xs[k * XP + n] = (node < NN) ? X[(size_t)node * FIN + kt + k] : 0.f;
        }
        #pragma unroll
        for (int l = tid; l < FOUT * KT; l += 256) {
            int f = l >> 5, k = l & 31;
            Ws[k * WP + f] = W[(size_t)f * FIN + kt + k];
        }
        __syncthreads();
        #pragma unroll
        for (int k = 0; k < KT; k++) {
            float4 xv = *(const float4*)&Xs[k * XP + 4 * r];
            #pragma unroll
            for (int j = 0; j < NJ; j++) {
                float4 wv = *(const float4*)&Ws[k * WP + j * 64 + 4 * c];
                const float xs[4] = {xv.x, xv.y, xv.z, xv.w};
                #pragma unroll
                for (int i = 0; i < 4; i++) {
                    acc[i][j][0] += xs[i] * wv.x;
                    acc[i][j][1] += xs[i] * wv.y;
                    acc[i][j][2] += xs[i] * wv.z;
                    acc[i][j][3] += xs[i] * wv.w;
                }
            }
        }
        __syncthreads();
    }

    // store H
    #pragma unroll
    for (int i = 0; i < 4; i++) {
        int node = nodeBase + 4 * r + i;
        if (node < NN) {
            #pragma unroll
            for (int j = 0; j < NJ; j++) {
                float4 o = make_float4(acc[i][j][0], acc[i][j][1],
                                       acc[i][j][2], acc[i][j][3]);
                *(float4*)&Hout[(size_t)node * FOUT + j * 64 + 4 * c] = o;
            }
        }
    }

    // fused attention coefficients: per-node dot with a_s / a_d
    float ps[4] = {0.f, 0.f, 0.f, 0.f};
    float pd[4] = {0.f, 0.f, 0.f, 0.f};
    #pragma unroll
    for (int j = 0; j < NJ; j++) {
        #pragma unroll
        for (int q = 0; q < 4; q++) {
            int col = j * 64 + 4 * c + q;
            float av = __ldg(&as_[col]);
            float dv = __ldg(&ad_[col]);
            #pragma unroll
            for (int i = 0; i < 4; i++) {
                ps[i] += acc[i][j][q] * av;
                pd[i] += acc[i][j][q] * dv;
            }
        }
    }
    // reduce over the 16 c-threads (contiguous lanes within half-warp)
    #pragma unroll
    for (int o = 1; o < 16; o <<= 1) {
        #pragma unroll
        for (int i = 0; i < 4; i++) {
            ps[i] += __shfl_xor_sync(0xffffffffu, ps[i], o);
            pd[i] += __shfl_xor_sync(0xffffffffu, pd[i], o);
        }
    }
    if (c == 0) {
        #pragma unroll
        for (int i = 0; i < 4; i++) {
            int node = nodeBase + 4 * r + i;
            if (node < NN) { g_es[node] = ps[i]; g_ed[node] = pd[i]; }
        }
    }
}

// ---------------- single-pass softmax + aggregation (one warp / node) ------
// Logits are O(+-1), so exp() without max-subtraction is safe; softmax is
// shift-invariant so the result matches the reference.
template <int F, bool RELU>
__global__ __launch_bounds__(256) void k_node(const float* __restrict__ Hm,
                                              float* __restrict__ Out,
                                              const float* __restrict__ bias) {
    __shared__ float s_ex[8][32];
    __shared__ int   s_src[8][32];
    const int wslot = threadIdx.x >> 5;
    const int v = (blockIdx.x * blockDim.x + threadIdx.x) >> 5;
    const int lane = threadIdx.x & 31;
    if (v >= NN) return;
    int beg = g_rowptr[v], end = g_rowptr[v + 1];
    beg = beg < 0 ? 0 : (beg > NE ? NE : beg);
    end = end < beg ? beg : (end > NE ? NE : end);
    const float edv = g_ed[v];

    constexpr int U = F / 32;
    float acc[U];
    #pragma unroll
    for (int u = 0; u < U; u++) acc[u] = 0.f;
    float ssum = 0.f;

    for (int base = beg; base < end; base += 32) {
        int j = base + lane;
        float ex = 0.f; int s = 0;
        if (j < end) {
            s = g_srcs[j];
            float ev = g_es[s] + edv;
            ev = ev > 0.f ? ev : 0.2f * ev;     // leaky_relu(0.2)
            ex = __expf(ev);
        }
        s_ex[wslot][lane] = ex;
        s_src[wslot][lane] = s;
        ssum += ex;
        __syncwarp();
        int cnt = end - base; cnt = cnt > 32 ? 32 : cnt;
        if (cnt == 32) {
            #pragma unroll 8
            for (int t = 0; t < 32; t++) {
                float a = s_ex[wslot][t];
                int  ss = s_src[wslot][t];
                #pragma unroll
                for (int u = 0; u < U; u++)
                    acc[u] += a * Hm[(size_t)ss * F + u * 32 + lane];
            }
        } else {
            for (int t = 0; t < cnt; t++) {
                float a = s_ex[wslot][t];
                int  ss = s_src[wslot][t];
                #pragma unroll
                for (int u = 0; u < U; u++)
                    acc[u] += a * Hm[(size_t)ss * F + u * 32 + lane];
            }
        }
        __syncwarp();
    }
    #pragma unroll
    for (int o = 16; o; o >>= 1) ssum += __shfl_xor_sync(0xffffffffu, ssum, o);
    const float inv = 1.f / (ssum + 1e-16f);

    #pragma unroll
    for (int u = 0; u < U; u++) {
        float o = acc[u] * inv + bias[u * 32 + lane];
        if (RELU) o = fmaxf(o, 0.f);
        Out[(size_t)v * F + u * 32 + lane] = o;
    }
}

// ---------------- launch ---------------------------------------------------
extern "C" void kernel_launch(void* const* d_in, const int* in_sizes, int n_in,
                              void* d_out, int out_size) {
    // Input mapping via size fingerprint (fc_w has 81,920,000 elements).
    int iz, ie, ifw, ifb, iW0, ias0, iad0, ib0, iW1, ias1, iad1, ib1, iW2, ias2, iad2, ib2;
    if (n_in >= 16 && in_sizes[14] == 81920000 && in_sizes[2] != 81920000) {
        iW0 = 0; iW1 = 1; iW2 = 2; iad0 = 3; iad1 = 4; iad2 = 5;
        ias0 = 6; ias1 = 7; ias2 = 8; ib0 = 9; ib1 = 10; ib2 = 11;
        ie = 12; ifb = 13; ifw = 14; iz = 15;
    } else {
        iz = 0; ie = 1; ifw = 2; ifb = 3;
        iW0 = 4; ias0 = 5; iad0 = 6; ib0 = 7;
        iW1 = 8; ias1 = 9; iad1 = 10; ib1 = 11;
        iW2 = 12; ias2 = 13; iad2 = 14; ib2 = 15;
    }

    const float* z    = (const float*)d_in[iz];
    const int*   eidx = (const int*)  d_in[ie];
    const float* fc_w = (const float*)d_in[ifw];
    const float* fc_b = (const float*)d_in[ifb];
    const float* W0   = (const float*)d_in[iW0];
    const float* as0  = (const float*)d_in[ias0];
    const float* ad0  = (const float*)d_in[iad0];
    const float* b0   = (const float*)d_in[ib0];
    const float* W1   = (const float*)d_in[iW1];
    const float* as1  = (const float*)d_in[ias1];
    const float* ad1  = (const float*)d_in[iad1];
    const float* b1   = (const float*)d_in[ib1];
    const float* W2   = (const float*)d_in[iW2];
    const float* as2  = (const float*)d_in[ias2];
    const float* ad2  = (const float*)d_in[iad2];
    const float* b2   = (const float*)d_in[ib2];
    float* out = (float*)d_out;

    // Device globals must be resolved to true device addresses (GB300 ATS trap).
    float *pX = nullptr, *pH = nullptr;
    cudaGetSymbolAddress((void**)&pX, g_X);
    cudaGetSymbolAddress((void**)&pH, g_H);

    // Persistent side stream + events for capture-legal fork/join.
    static cudaStream_t s1 = nullptr;
    static cudaEvent_t evF = nullptr, evJ = nullptr;
    if (!s1) {
        cudaStreamCreateWithFlags(&s1, cudaStreamNonBlocking);
        cudaEventCreateWithFlags(&evF, cudaEventDisableTiming);
        cudaEventCreateWithFlags(&evJ, cudaEventDisableTiming);
    }

    const int TB = 256;
    const int gN   = (NN + TB - 1) / TB;                 // 79
    const int gE   = (NE + TB - 1) / TB;                 // 2500
    const int gFC  = (NN * LAT / 2 * 32 + TB - 1) / TB;  // 80000
    const int gW   = (NN * 32 + TB - 1) / TB;            // 2500
    const int gG   = (NN + 63) / 64;                     // 313
    const int gS   = (NN + 1023) / 1024;                 // 20

    // fork: CSR build on side stream, overlapped with fc + gemm0
    cudaEventRecord(evF, 0);
    cudaStreamWaitEvent(s1, evF, 0);

    k_zero_deg<<<gN, TB, 0, s1>>>();
    k_detect<<<gE, TB, 0, s1>>>(eidx);
    k_convert_hist<<<gE, TB, 0, s1>>>(eidx);
    k_scan1<<<gS, 1024, 0, s1>>>();
    k_scan2<<<1, 32, 0, s1>>>(gS);
    k_scan3<<<gS, 1024, 0, s1>>>();
    k_scatter<<<gE, TB, 0, s1>>>();
    cudaEventRecord(evJ, s1);

    // main stream: fc -> gemm0 (+attn fused)
    k_fc<<<gFC, TB>>>(fc_w, fc_b, z);
    k_gemm<LAT, HID><<<gG, TB>>>(pX, W0, as0, ad0, pH);

    // join: node needs CSR
    cudaStreamWaitEvent(0, evJ, 0);

    // layer 0 aggregate, then layers 1 and 2
    k_node<HID, true><<<gW, TB>>>(pH, pX, b0);

    k_gemm<HID, HID><<<gG, TB>>>(pX, W1, as1, ad1, pH);
    k_node<HID, true><<<gW, TB>>>(pH, pX, b1);

    k_gemm<HID, NF><<<gG, TB>>>(pX, W2, as2, ad2, pH);
    k_node<NF, false><<<gW, TB>>>(pH, out, b2);
}

// round 17
// speedup vs baseline: 1.2922x; 1.2922x over previous
#include <cuda_runtime.h>

// Problem constants
constexpr int NN = 20000;    // nodes
constexpr int NE = 640000;   // edges
constexpr int LAT = 64;
constexpr int HID = 128;
constexpr int NF  = 64;

// ---------------- scratch (device globals; no allocation allowed) -----------
__device__ int   g_is64;
__device__ int   g_src32[NE];
__device__ int   g_dst32[NE];
__device__ int   g_deg[NN];
__device__ int   g_rowptr[NN + 1];
__device__ int   g_cursor[NN];
__device__ int   g_bsum[32];
__device__ int   g_boff[32];
__device__ int   g_srcs[NE];        // src node per edge, sorted by dst (CSR)
__device__ float g_X[NN * HID];     // layer input features
__device__ float g_H[NN * HID];     // transformed features h = x @ W^T
__device__ float g_es[NN];          // h . a_s per node
__device__ float g_ed[NN];          // h . a_d per node

__device__ __forceinline__ int clampN(int v) {
    v = v < 0 ? 0 : v;
    return v >= NN ? NN - 1 : v;
}

// ---------------- CSR build ------------------------------------------------
__global__ __launch_bounds__(256) void k_zero_deg() {
    int i = blockIdx.x * blockDim.x + threadIdx.x;
    if (i < NN) g_deg[i] = 0;
    if (i == 0) g_is64 = 0;
}

// int64 node ids (< 2^31, >= 0) => every odd int32 word of first 2*NE words is 0.
__global__ __launch_bounds__(256) void k_detect(const int* __restrict__ e) {
    int i = blockIdx.x * blockDim.x + threadIdx.x;
    int v = (i < NE) ? e[2 * i + 1] : 0;
    #pragma unroll
    for (int o = 16; o; o >>= 1) v |= __shfl_xor_sync(0xffffffffu, v, o);
    if ((threadIdx.x & 31) == 0 && v != 0) atomicOr(&g_is64, 1);
}

// fused convert + degree histogram
__global__ __launch_bounds__(256) void k_convert_hist(const int* __restrict__ e) {
    int i = blockIdx.x * blockDim.x + threadIdx.x;
    if (i >= NE) return;
    int s, d;
    if (g_is64 == 0) {   // all high words zero -> int64 layout
        const long long* e64 = (const long long*)e;
        s = (int)e64[i];
        d = (int)e64[NE + i];
    } else {             // int32 layout
        s = e[i];
        d = e[NE + i];
    }
    s = clampN(s); d = clampN(d);
    g_src32[i] = s;
    g_dst32[i] = d;
    atomicAdd(&g_deg[d], 1);
}

// ---- multi-block exclusive scan: local scan -> block sums -> add offsets ---
__global__ __launch_bounds__(1024) void k_scan1() {
    __shared__ int wsum[32];
    __shared__ int woff[32];
    const int tid = threadIdx.x, lane = tid & 31, wid = tid >> 5;
    const int i = blockIdx.x * 1024 + tid;
    int v = (i < NN) ? g_deg[i] : 0;
    int x = v;
    #pragma unroll
    for (int o = 1; o < 32; o <<= 1) {
        int y = __shfl_up_sync(0xffffffffu, x, o);
        if (lane >= o) x += y;
    }
    if (lane == 31) wsum[wid] = x;
    __syncthreads();
    if (wid == 0) {
        int w = wsum[lane];
        int incl = w;
        #pragma unroll
        for (int o = 1; o < 32; o <<= 1) {
            int y = __shfl_up_sync(0xffffffffu, incl, o);
            if (lane >= o) incl += y;
        }
        woff[lane] = incl - w;
        if (lane == 31) g_bsum[blockIdx.x] = incl;
    }
    __syncthreads();
    int incl = x + woff[wid];
    if (i < NN) g_rowptr[i + 1] = incl;      // block-local inclusive
}

__global__ __launch_bounds__(32) void k_scan2(int nblk) {
    int lane = threadIdx.x;
    int v = (lane < nblk) ? g_bsum[lane] : 0;
    int incl = v;
    #pragma unroll
    for (int o = 1; o < 32; o <<= 1) {
        int y = __shfl_up_sync(0xffffffffu, incl, o);
        if (lane >= o) incl += y;
    }
    if (lane < nblk) g_boff[lane] = incl - v;   // exclusive
    if (lane == 0) g_rowptr[0] = 0;
}

__global__ __launch_bounds__(1024) void k_scan3() {
    const int i = blockIdx.x * 1024 + threadIdx.x;
    if (i < NN) {
        int rp = g_rowptr[i + 1] + g_boff[blockIdx.x];
        g_rowptr[i + 1] = rp;
        g_cursor[i] = rp - g_deg[i];
    }
}

__global__ __launch_bounds__(256) void k_scatter() {
    int i = blockIdx.x * blockDim.x + threadIdx.x;
    if (i < NE) {
        int d = g_dst32[i];
        int pos = atomicAdd(&g_cursor[d], 1);
        if (pos >= 0 && pos < NE) g_srcs[pos] = g_src32[i];
    }
}

// ---------------- fc: x = relu(z @ fc_w.T + fc_b) into g_X -----------------
__global__ __launch_bounds__(256) void k_fc(const float* __restrict__ w,
                                            const float* __restrict__ b,
                                            const float* __restrict__ z) {
    const int wid  = (blockIdx.x * blockDim.x + threadIdx.x) >> 5;
    const int lane = threadIdx.x & 31;
    const int half = lane >> 4;
    const int sub  = lane & 15;
    const int row  = wid * 2 + half;
    if (row >= NN * LAT) return;

    float4 wv = ((const float4*)(w + (size_t)row * LAT))[sub];
    float4 zv = ((const float4*)z)[sub];
    float acc = wv.x * zv.x + wv.y * zv.y + wv.z * zv.z + wv.w * zv.w;
    #pragma unroll
    for (int o = 8; o; o >>= 1) acc += __shfl_xor_sync(0xffffffffu, acc, o);
    if (sub == 0) {
        acc += b[row];
        g_X[row] = acc > 0.f ? acc : 0.f;
    }
}

// ---------------- GEMM + fused attention coefficients ----------------------
// H[n][f] = dot(X[n][:FIN], W[f][:FIN]); also es[n]=H[n]·a_s, ed[n]=H[n]·a_d
// computed in-register (half-warp shuffle reduction over the 16 c-threads).
template <int FIN, int FOUT>
__global__ __launch_bounds__(256) void k_gemm(const float* __restrict__ X,
                                              const float* __restrict__ W,
                                              const float* __restrict__ as_,
                                              const float* __restrict__ ad_,
                                              float* __restrict__ Hout) {
    constexpr int KT = 32;
    constexpr int XP = 64 + 4;
    constexpr int WP = FOUT + 4;
    constexpr int NJ = FOUT / 64;
    __shared__ float Xs[KT * XP];
    __shared__ float Ws[KT * WP];
    const int tid = threadIdx.x;
    const int r = tid >> 4;           // 0..15 -> nodes 4r..4r+3
    const int c = tid & 15;           // cols 4c..4c+3 (+64 if NJ==2)
    const int nodeBase = blockIdx.x * 64;

    float acc[4][NJ][4];
    #pragma unroll
    for (int i = 0; i < 4; i++)
        #pragma unroll
        for (int j = 0; j < NJ; j++)
            #pragma unroll
            for (int q = 0; q < 4; q++) acc[i][j][q] = 0.f;

    for (int kt = 0; kt < FIN; kt += KT) {
        #pragma unroll
        for (int l = tid; l < 64 * KT; l += 256) {
            int n = l >> 5, k = l & 31;
            int node = nodeBase + n;
            Xs[k * XP + n] = (node < NN) ? X[(size_t)node * FIN + kt + k] : 0.f;
        }
        #pragma unroll
        for (int l = tid; l < FOUT * KT; l += 256) {
            int f = l >> 5, k = l & 31;
            Ws[k * WP + f] = W[(size_t)f * FIN + kt + k];
        }
        __syncthreads();
        #pragma unroll
        for (int k = 0; k < KT; k++) {
            float4 xv = *(const float4*)&Xs[k * XP + 4 * r];
            #pragma unroll
            for (int j = 0; j < NJ; j++) {
                float4 wv = *(const float4*)&Ws[k * WP + j * 64 + 4 * c];
                const float xs[4] = {xv.x, xv.y, xv.z, xv.w};
                #pragma unroll
                for (int i = 0; i < 4; i++) {
                    acc[i][j][0] += xs[i] * wv.x;
                    acc[i][j][1] += xs[i] * wv.y;
                    acc[i][j][2] += xs[i] * wv.z;
                    acc[i][j][3] += xs[i] * wv.w;
                }
            }
        }
        __syncthreads();
    }

    // store H
    #pragma unroll
    for (int i = 0; i < 4; i++) {
        int node = nodeBase + 4 * r + i;
        if (node < NN) {
            #pragma unroll
            for (int j = 0; j < NJ; j++) {
                float4 o = make_float4(acc[i][j][0], acc[i][j][1],
                                       acc[i][j][2], acc[i][j][3]);
                *(float4*)&Hout[(size_t)node * FOUT + j * 64 + 4 * c] = o;
            }
        }
    }

    // fused attention coefficients: per-node dot with a_s / a_d
    float ps[4] = {0.f, 0.f, 0.f, 0.f};
    float pd[4] = {0.f, 0.f, 0.f, 0.f};
    #pragma unroll
    for (int j = 0; j < NJ; j++) {
        #pragma unroll
        for (int q = 0; q < 4; q++) {
            int col = j * 64 + 4 * c + q;
            float av = __ldg(&as_[col]);
            float dv = __ldg(&ad_[col]);
            #pragma unroll
            for (int i = 0; i < 4; i++) {
                ps[i] += acc[i][j][q] * av;
                pd[i] += acc[i][j][q] * dv;
            }
        }
    }
    // reduce over the 16 c-threads (contiguous lanes within half-warp)
    #pragma unroll
    for (int o = 1; o < 16; o <<= 1) {
        #pragma unroll
        for (int i = 0; i < 4; i++) {
            ps[i] += __shfl_xor_sync(0xffffffffu, ps[i], o);
            pd[i] += __shfl_xor_sync(0xffffffffu, pd[i], o);
        }
    }
    if (c == 0) {
        #pragma unroll
        for (int i = 0; i < 4; i++) {
            int node = nodeBase + 4 * r + i;
            if (node < NN) { g_es[node] = ps[i]; g_ed[node] = pd[i]; }
        }
    }
}

// ---------------- single-pass softmax + aggregation (one warp / node) ------
// Logits are O(+-1), so exp() without max-subtraction is safe; softmax is
// shift-invariant so the result matches the reference.
template <int F, bool RELU>
__global__ __launch_bounds__(256) void k_node(const float* __restrict__ Hm,
                                              float* __restrict__ Out,
                                              const float* __restrict__ bias) {
    __shared__ float s_ex[8][32];
    __shared__ int   s_src[8][32];
    const int wslot = threadIdx.x >> 5;
    const int v = (blockIdx.x * blockDim.x + threadIdx.x) >> 5;
    const int lane = threadIdx.x & 31;
    if (v >= NN) return;
    int beg = g_rowptr[v], end = g_rowptr[v + 1];
    beg = beg < 0 ? 0 : (beg > NE ? NE : beg);
    end = end < beg ? beg : (end > NE ? NE : end);
    const float edv = g_ed[v];

    constexpr int U = F / 32;
    float acc[U];
    #pragma unroll
    for (int u = 0; u < U; u++) acc[u] = 0.f;
    float ssum = 0.f;

    for (int base = beg; base < end; base += 32) {
        int j = base + lane;
        float ex = 0.f; int s = 0;
        if (j < end) {
            s = g_srcs[j];
            float ev = g_es[s] + edv;
            ev = ev > 0.f ? ev : 0.2f * ev;     // leaky_relu(0.2)
            ex = __expf(ev);
        }
        s_ex[wslot][lane] = ex;
        s_src[wslot][lane] = s;
        ssum += ex;
        __syncwarp();
        int cnt = end - base; cnt = cnt > 32 ? 32 : cnt;
        if (cnt == 32) {
            #pragma unroll 8
            for (int t = 0; t < 32; t++) {
                float a = s_ex[wslot][t];
                int  ss = s_src[wslot][t];
                #pragma unroll
                for (int u = 0; u < U; u++)
                    acc[u] += a * Hm[(size_t)ss * F + u * 32 + lane];
            }
        } else {
            for (int t = 0; t < cnt; t++) {
                float a = s_ex[wslot][t];
                int  ss = s_src[wslot][t];
                #pragma unroll
                for (int u = 0; u < U; u++)
                    acc[u] += a * Hm[(size_t)ss * F + u * 32 + lane];
            }
        }
        __syncwarp();
    }
    #pragma unroll
    for (int o = 16; o; o >>= 1) ssum += __shfl_xor_sync(0xffffffffu, ssum, o);
    const float inv = 1.f / (ssum + 1e-16f);

    #pragma unroll
    for (int u = 0; u < U; u++) {
        float o = acc[u] * inv + bias[u * 32 + lane];
        if (RELU) o = fmaxf(o, 0.f);
        Out[(size_t)v * F + u * 32 + lane] = o;
    }
}

// ---------------- launch ---------------------------------------------------
extern "C" void kernel_launch(void* const* d_in, const int* in_sizes, int n_in,
                              void* d_out, int out_size) {
    // Input mapping via size fingerprint (fc_w has 81,920,000 elements).
    int iz, ie, ifw, ifb, iW0, ias0, iad0, ib0, iW1, ias1, iad1, ib1, iW2, ias2, iad2, ib2;
    if (n_in >= 16 && in_sizes[14] == 81920000 && in_sizes[2] != 81920000) {
        iW0 = 0; iW1 = 1; iW2 = 2; iad0 = 3; iad1 = 4; iad2 = 5;
        ias0 = 6; ias1 = 7; ias2 = 8; ib0 = 9; ib1 = 10; ib2 = 11;
        ie = 12; ifb = 13; ifw = 14; iz = 15;
    } else {
        iz = 0; ie = 1; ifw = 2; ifb = 3;
        iW0 = 4; ias0 = 5; iad0 = 6; ib0 = 7;
        iW1 = 8; ias1 = 9; iad1 = 10; ib1 = 11;
        iW2 = 12; ias2 = 13; iad2 = 14; ib2 = 15;
    }

    const float* z    = (const float*)d_in[iz];
    const int*   eidx = (const int*)  d_in[ie];
    const float* fc_w = (const float*)d_in[ifw];
    const float* fc_b = (const float*)d_in[ifb];
    const float* W0   = (const float*)d_in[iW0];
    const float* as0  = (const float*)d_in[ias0];
    const float* ad0  = (const float*)d_in[iad0];
    const float* b0   = (const float*)d_in[ib0];
    const float* W1   = (const float*)d_in[iW1];
    const float* as1  = (const float*)d_in[ias1];
    const float* ad1  = (const float*)d_in[iad1];
    const float* b1   = (const float*)d_in[ib1];
    const float* W2   = (const float*)d_in[iW2];
    const float* as2  = (const float*)d_in[ias2];
    const float* ad2  = (const float*)d_in[iad2];
    const float* b2   = (const float*)d_in[ib2];
    float* out = (float*)d_out;

    // Device globals must be resolved to true device addresses (GB300 ATS trap).
    float *pX = nullptr, *pH = nullptr;
    cudaGetSymbolAddress((void**)&pX, g_X);
    cudaGetSymbolAddress((void**)&pH, g_H);

    const int TB = 256;
    const int gN   = (NN + TB - 1) / TB;                 // 79
    const int gE   = (NE + TB - 1) / TB;                 // 2500
    const int gFC  = (NN * LAT / 2 * 32 + TB - 1) / TB;  // 80000
    const int gW   = (NN * 32 + TB - 1) / TB;            // 2500
    const int gG   = (NN + 63) / 64;                     // 313
    const int gS   = (NN + 1023) / 1024;                 // 20

    // CSR build (single stream — fork/join measured as a 60us regression)
    k_zero_deg<<<gN, TB>>>();
    k_detect<<<gE, TB>>>(eidx);
    k_convert_hist<<<gE, TB>>>(eidx);
    k_scan1<<<gS, 1024>>>();
    k_scan2<<<1, 32>>>(gS);
    k_scan3<<<gS, 1024>>>();
    k_scatter<<<gE, TB>>>();

    // fc
    k_fc<<<gFC, TB>>>(fc_w, fc_b, z);

    // layer 0: 64 -> 128, relu
    k_gemm<LAT, HID><<<gG, TB>>>(pX, W0, as0, ad0, pH);
    k_node<HID, true><<<gW, TB>>>(pH, pX, b0);

    // layer 1: 128 -> 128, relu
    k_gemm<HID, HID><<<gG, TB>>>(pX, W1, as1, ad1, pH);
    k_node<HID, true><<<gW, TB>>>(pH, pX, b1);

    // layer 2: 128 -> 64, no relu, straight to output
    k_gemm<HID, NF><<<gG, TB>>>(pX, W2, as2, ad2, pH);
    k_node<NF, false><<<gW, TB>>>(pH, out, b2);
}